// round 4
// baseline (speedup 1.0000x reference)
#include <cuda_runtime.h>
#include <math.h>

#define HD 64
#define MAXN 100000
#define MAXE 1200000
#define MAXB 1000
#define BN_EPS 1e-5f
#define STAGE_CAP 4096

typedef unsigned long long u64;

// Scratch (__device__ globals: allocation-free rule; zero-initialized at load,
// re-zeroed at the END of every launch by final_kernel)
__device__ float g_h[MAXN * HD];
__device__ float g_pool[MAXB * HD];
__device__ int   g_deg[MAXN];
__device__ int2  g_row2[MAXN];     // {rowptr, deg}
__device__ int   g_cursor[MAXN];
__device__ int   g_csr[MAXE];
__device__ u64   g_state[128];     // decoupled-lookback scan states

#define FLAG_AGG (1ull << 62)
#define FLAG_PRE (2ull << 62)

__device__ __forceinline__ void red_add_f4(float* p, float4 v) {
    asm volatile("red.global.add.v4.f32 [%0], {%1, %2, %3, %4};"
                 :: "l"(p), "f"(v.x), "f"(v.y), "f"(v.z), "f"(v.w)
                 : "memory");
}
__device__ __forceinline__ u64 pack2(float x, float y) {
    u64 r; asm("mov.b64 %0, {%1, %2};" : "=l"(r) : "f"(x), "f"(y)); return r;
}
__device__ __forceinline__ float2 unpack2(u64 v) {
    float2 f; asm("mov.b64 {%0, %1}, %2;" : "=f"(f.x), "=f"(f.y) : "l"(v)); return f;
}
__device__ __forceinline__ void ffma2(u64& d, u64 a, u64 b) {
    asm("fma.rn.f32x2 %0, %1, %2, %0;" : "+l"(d) : "l"(a), "l"(b));
}

// ---------------------------------------------------------------------------
// K1: histogram of dst (deg was zeroed by previous launch / initial state)
// ---------------------------------------------------------------------------
__global__ void hist_kernel(const int* __restrict__ ei, int E) {
    int e = blockIdx.x * blockDim.x + threadIdx.x;
    if (e < E) atomicAdd(&g_deg[ei[E + e]], 1);
}

// ---------------------------------------------------------------------------
// K2: single-pass exclusive scan (decoupled lookback), emits row2 + cursor
// ---------------------------------------------------------------------------
__global__ __launch_bounds__(1024) void scan_kernel(int N) {
    int b = blockIdx.x;
    int tid = threadIdx.x;
    int i = b * 1024 + tid;
    int v = (i < N) ? g_deg[i] : 0;
    int x = v;
    #pragma unroll
    for (int o = 1; o < 32; o <<= 1) {
        int y = __shfl_up_sync(0xFFFFFFFFu, x, o);
        if ((tid & 31) >= o) x += y;
    }
    __shared__ int ws[32];
    __shared__ int s_agg;
    __shared__ int s_excl;
    if ((tid & 31) == 31) ws[tid >> 5] = x;
    __syncthreads();
    if (tid < 32) {
        int y = ws[tid];
        #pragma unroll
        for (int o = 1; o < 32; o <<= 1) {
            int z = __shfl_up_sync(0xFFFFFFFFu, y, o);
            if (tid >= o) y += z;
        }
        ws[tid] = y;
    }
    __syncthreads();
    int base = (tid >= 32) ? ws[(tid >> 5) - 1] : 0;
    int incl = x + base;
    if (tid == 1023) s_agg = incl;
    __syncthreads();
    int agg = s_agg;

    if (tid < 32) {
        if (tid == 0) {
            u64 st = (b == 0 ? FLAG_PRE : FLAG_AGG) | (unsigned)agg;
            atomicExch(&g_state[b], st);
        }
        int excl = 0;
        if (b > 0) {
            int j = b - 1;
            bool done = false;
            while (!done) {
                int idx = j - tid;
                u64 s;
                if (idx >= 0) s = *(volatile u64*)&g_state[idx];
                else          s = FLAG_PRE;
                unsigned flag = (unsigned)(s >> 62);
                int val = (int)(unsigned)(s & 0xFFFFFFFFull);
                unsigned pmask = __ballot_sync(0xFFFFFFFFu, flag == 2u);
                unsigned rmask = __ballot_sync(0xFFFFFFFFu, flag >= 1u);
                if (pmask) {
                    int lead = __ffs(pmask) - 1;
                    unsigned need = (lead == 31) ? 0xFFFFFFFFu : ((1u << (lead + 1)) - 1u);
                    if ((rmask & need) == need) {
                        int contrib = (tid <= lead) ? val : 0;
                        #pragma unroll
                        for (int o = 16; o; o >>= 1)
                            contrib += __shfl_down_sync(0xFFFFFFFFu, contrib, o);
                        excl += __shfl_sync(0xFFFFFFFFu, contrib, 0);
                        done = true;
                    }
                } else if (rmask == 0xFFFFFFFFu) {
                    int contrib = val;
                    #pragma unroll
                    for (int o = 16; o; o >>= 1)
                        contrib += __shfl_down_sync(0xFFFFFFFFu, contrib, o);
                    excl += __shfl_sync(0xFFFFFFFFu, contrib, 0);
                    j -= 32;
                }
            }
            if (tid == 0)
                atomicExch(&g_state[b], FLAG_PRE | (unsigned)(excl + agg));
        }
        if (tid == 0) s_excl = excl;
    }
    __syncthreads();
    int rowp = s_excl + incl - v;
    if (i < N) {
        g_row2[i] = make_int2(rowp, v);
        g_cursor[i] = rowp;
    }
}

// K3: bucket edges by dst: csr[pos] = src
__global__ void permute_kernel(const int* __restrict__ ei, int E) {
    int e = blockIdx.x * blockDim.x + threadIdx.x;
    if (e < E) {
        int d = ei[E + e];
        int pos = atomicAdd(&g_cursor[d], 1);
        g_csr[pos] = ei[e];
    }
}

// ---------------------------------------------------------------------------
// Gather with smem-staged CSR segment + double-buffered pipelined walk.
// Block covers 128 rows, 512 threads; tasks = 128 rows x 16 float4 chunks.
// ---------------------------------------------------------------------------
__device__ __forceinline__ float4 ldf4(const float* __restrict__ src, int n, int c) {
    return ((const float4*)src)[n * 16 + c];
}

__device__ __forceinline__ void gather_tile(const float* __restrict__ src,
                                            float* tile, int* sidx,
                                            int rowBase, int N, int tid) {
    int rend = min(rowBase + 127, N - 1);
    int2 first = g_row2[rowBase];
    int2 last  = g_row2[rend];
    int segStart = first.x;
    int segLen = last.x + last.y - segStart;
    int stage = min(segLen, STAGE_CAP);
    for (int i = tid; i < stage; i += 512) sidx[i] = g_csr[segStart + i];
    __syncthreads();

    #pragma unroll
    for (int t4 = 0; t4 < 4; t4++) {
        int task = tid + t4 * 512;
        int lr = task >> 4, c = task & 15;
        int g = rowBase + lr;
        float4 a = make_float4(0.f, 0.f, 0.f, 0.f);
        if (g < N) {
            a = ldf4(src, g, c);
            int2 rd = g_row2[g];
            int j = rd.x - segStart;
            int e = j + rd.y;
            int eS = min(e, stage);
            if (eS - j >= 8) {
                // preload group 0
                int n0 = sidx[j], n1 = sidx[j+1], n2 = sidx[j+2], n3 = sidx[j+3];
                float4 p0 = ldf4(src, n0, c), p1 = ldf4(src, n1, c);
                float4 p2 = ldf4(src, n2, c), p3 = ldf4(src, n3, c);
                j += 4;
                while (eS - j >= 4) {
                    int m0 = sidx[j], m1 = sidx[j+1], m2 = sidx[j+2], m3 = sidx[j+3];
                    float4 q0 = ldf4(src, m0, c), q1 = ldf4(src, m1, c);
                    float4 q2 = ldf4(src, m2, c), q3 = ldf4(src, m3, c);
                    a.x += (p0.x + p1.x) + (p2.x + p3.x);
                    a.y += (p0.y + p1.y) + (p2.y + p3.y);
                    a.z += (p0.z + p1.z) + (p2.z + p3.z);
                    a.w += (p0.w + p1.w) + (p2.w + p3.w);
                    p0 = q0; p1 = q1; p2 = q2; p3 = q3;
                    j += 4;
                }
                a.x += (p0.x + p1.x) + (p2.x + p3.x);
                a.y += (p0.y + p1.y) + (p2.y + p3.y);
                a.z += (p0.z + p1.z) + (p2.z + p3.z);
                a.w += (p0.w + p1.w) + (p2.w + p3.w);
            }
            for (; j < eS; j++) {
                float4 v0 = ldf4(src, sidx[j], c);
                a.x += v0.x; a.y += v0.y; a.z += v0.z; a.w += v0.w;
            }
            for (; j < e; j++) {   // stage-cap overflow (rare)
                float4 v0 = ldf4(src, g_csr[segStart + j], c);
                a.x += v0.x; a.y += v0.y; a.z += v0.z; a.w += v0.w;
            }
        }
        float* tp = tile + lr * 65 + c * 4;
        tp[0] = a.x; tp[1] = a.y; tp[2] = a.z; tp[3] = a.w;
    }
}

// One-row GEMM step: acc[8] (u64 = 2 floats) += a * W[k, colBase..colBase+15]
__device__ __forceinline__ void gemm_row(u64* acc, const float* tile, const float* W,
                                         int rp, int colBase) {
    #pragma unroll
    for (int k = 0; k < 64; k++) {
        float a = tile[rp * 65 + k];
        u64 A = pack2(a, a);
        const ulonglong2* w = (const ulonglong2*)(W + k * 64 + colBase);
        #pragma unroll
        for (int j2 = 0; j2 < 4; j2++) {
            ulonglong2 ww = w[j2];
            ffma2(acc[j2 * 2],     A, ww.x);
            ffma2(acc[j2 * 2 + 1], A, ww.y);
        }
    }
}

extern __shared__ float sdyn[];

// ---------------------------------------------------------------------------
// K4: mlp1: gather(x) -> GEMM(W1a)+BN+ReLU -> GEMM(W1b)+ReLU -> g_h
// 512 threads, 128 rows, 1 row x 16 cols per thread.
// sidx overlays the Wb region; weights loaded after the gather.
// ---------------------------------------------------------------------------
__global__ __launch_bounds__(512, 2) void mlp1_kernel(
    const float* __restrict__ x,
    const float* __restrict__ W1a, const float* __restrict__ b1a,
    const float* __restrict__ g1,  const float* __restrict__ be1,
    const float* __restrict__ m1,  const float* __restrict__ v1,
    const float* __restrict__ W1b, const float* __restrict__ b1b,
    int N) {
    float* Wa   = sdyn;                 // 4096
    float* Wb   = sdyn + 4096;          // 4096 (sidx overlay during gather)
    float* tile = sdyn + 8192;          // 128*65
    float* s1   = tile + 128 * 65;      // 64
    float* t1   = s1 + 64;              // 64
    int* sidx   = (int*)Wb;

    int tid = threadIdx.x;
    // Wa load can happen before gather (doesn't overlap sidx)
    #pragma unroll
    for (int i = 0; i < 2; i++)
        ((float4*)Wa)[tid + 512 * i] = ((const float4*)W1a)[tid + 512 * i];
    if (tid < 64) {
        float s = g1[tid] * rsqrtf(v1[tid] + BN_EPS);
        s1[tid] = s;
        t1[tid] = be1[tid] - m1[tid] * s;
    }
    int rowBase = blockIdx.x * 128;
    gather_tile(x, tile, sidx, rowBase, N, tid);
    __syncthreads();   // gather done (sidx reads complete)

    // now load W1b over the sidx region
    #pragma unroll
    for (int i = 0; i < 2; i++)
        ((float4*)Wb)[tid + 512 * i] = ((const float4*)W1b)[tid + 512 * i];
    __syncthreads();

    int rp = tid >> 2, q = tid & 3, colBase = q * 16;

    u64 acc[8];
    #pragma unroll
    for (int j = 0; j < 8; j++)
        acc[j] = pack2(b1a[colBase + 2 * j], b1a[colBase + 2 * j + 1]);
    gemm_row(acc, tile, Wa, rp, colBase);
    __syncthreads();   // all tile reads done before overwrite

    #pragma unroll
    for (int j = 0; j < 8; j++) {
        int c0 = colBase + 2 * j;
        float2 p = unpack2(acc[j]);
        tile[rp * 65 + c0]     = fmaxf(p.x * s1[c0]     + t1[c0],     0.f);
        tile[rp * 65 + c0 + 1] = fmaxf(p.y * s1[c0 + 1] + t1[c0 + 1], 0.f);
    }
    __syncthreads();

    #pragma unroll
    for (int j = 0; j < 8; j++)
        acc[j] = pack2(b1b[colBase + 2 * j], b1b[colBase + 2 * j + 1]);
    gemm_row(acc, tile, Wb, rp, colBase);

    int gr = rowBase + rp;
    if (gr < N) {
        #pragma unroll
        for (int j4 = 0; j4 < 4; j4++) {
            float2 pa = unpack2(acc[j4 * 2]), pb = unpack2(acc[j4 * 2 + 1]);
            float4 y = make_float4(fmaxf(pa.x, 0.f), fmaxf(pa.y, 0.f),
                                   fmaxf(pb.x, 0.f), fmaxf(pb.y, 0.f));
            ((float4*)(g_h + gr * HD + colBase))[j4] = y;
        }
    }
}

// ---------------------------------------------------------------------------
// K5: mlp2: gather(h) -> GEMM(W2)+BN+ReLU -> pool[batch] += (REDG.128)
// sidx overlays Wa; W2 loaded after gather.
// ---------------------------------------------------------------------------
__global__ __launch_bounds__(512, 2) void mlp2_kernel(
    const float* __restrict__ W2, const float* __restrict__ b2,
    const float* __restrict__ g2, const float* __restrict__ be2,
    const float* __restrict__ m2, const float* __restrict__ v2,
    const int* __restrict__ batch, int N) {
    float* Wa   = sdyn;                 // 4096 (sidx overlay during gather)
    float* tile = sdyn + 4096;          // 128*65
    float* s1   = tile + 128 * 65;      // 64
    float* t1   = s1 + 64;              // 64
    int* sidx   = (int*)Wa;

    int tid = threadIdx.x;
    if (tid < 64) {
        float s = g2[tid] * rsqrtf(v2[tid] + BN_EPS);
        s1[tid] = s;
        t1[tid] = be2[tid] - m2[tid] * s;
    }
    int rowBase = blockIdx.x * 128;
    gather_tile(g_h, tile, sidx, rowBase, N, tid);
    __syncthreads();

    #pragma unroll
    for (int i = 0; i < 2; i++)
        ((float4*)Wa)[tid + 512 * i] = ((const float4*)W2)[tid + 512 * i];
    __syncthreads();

    int rp = tid >> 2, q = tid & 3, colBase = q * 16;

    u64 acc[8];
    #pragma unroll
    for (int j = 0; j < 8; j++)
        acc[j] = pack2(b2[colBase + 2 * j], b2[colBase + 2 * j + 1]);
    gemm_row(acc, tile, Wa, rp, colBase);

    int gr = rowBase + rp;
    if (gr < N) {
        int b = batch[gr];
        float* pp = g_pool + b * HD + colBase;
        #pragma unroll
        for (int j4 = 0; j4 < 4; j4++) {
            int c0 = colBase + j4 * 4;
            float2 pa = unpack2(acc[j4 * 2]), pb = unpack2(acc[j4 * 2 + 1]);
            float4 y = make_float4(
                fmaxf(pa.x * s1[c0]     + t1[c0],     0.f),
                fmaxf(pa.y * s1[c0 + 1] + t1[c0 + 1], 0.f),
                fmaxf(pb.x * s1[c0 + 2] + t1[c0 + 2], 0.f),
                fmaxf(pb.y * s1[c0 + 3] + t1[c0 + 3], 0.f));
            red_add_f4(pp + j4 * 4, y);
        }
    }
}

// ---------------------------------------------------------------------------
// K6: per graph: xt = relu(topo@Wt+bt); out = [pool, xt] @ Wc + bc
// Also: cleanup for next replay (zero deg/state and pool-after-read).
// ---------------------------------------------------------------------------
__global__ void final_kernel(const float* __restrict__ topo,
                             const float* __restrict__ Wt, const float* __restrict__ bt,
                             const float* __restrict__ Wc, const float* __restrict__ bc,
                             float* __restrict__ out, int B, int C, int N) {
    int b = blockIdx.x;
    int t = threadIdx.x;   // 64
    __shared__ float comb[128];

    float acc = bt[t];
    #pragma unroll
    for (int k = 0; k < 64; k++)
        acc += topo[b * 64 + k] * Wt[k * 64 + t];
    comb[64 + t] = fmaxf(acc, 0.f);
    comb[t] = g_pool[b * HD + t];
    __syncthreads();

    if (t < C) {
        float o = bc[t];
        #pragma unroll
        for (int k = 0; k < 128; k++)
            o += comb[k] * Wc[k * C + t];
        out[b * C + t] = o;
    }

    // cleanup for next replay
    g_pool[b * HD + t] = 0.f;                 // read above (pre-sync), safe
    int gidx = b * 64 + t;
    for (int i = gidx; i < N; i += B * 64) g_deg[i] = 0;
    if (gidx < 128) g_state[gidx] = 0ull;
}

// ---------------------------------------------------------------------------
extern "C" void kernel_launch(void* const* d_in, const int* in_sizes, int n_in,
                              void* d_out, int out_size) {
    const float* x     = (const float*)d_in[0];
    const int*   ei    = (const int*)  d_in[1];
    const int*   batch = (const int*)  d_in[2];
    const float* topo  = (const float*)d_in[3];
    const float* W1a = (const float*)d_in[4];
    const float* b1a = (const float*)d_in[5];
    const float* g1  = (const float*)d_in[6];
    const float* be1 = (const float*)d_in[7];
    const float* m1  = (const float*)d_in[8];
    const float* v1  = (const float*)d_in[9];
    const float* W1b = (const float*)d_in[10];
    const float* b1b = (const float*)d_in[11];
    const float* W2  = (const float*)d_in[12];
    const float* b2  = (const float*)d_in[13];
    const float* g2  = (const float*)d_in[14];
    const float* be2 = (const float*)d_in[15];
    const float* m2  = (const float*)d_in[16];
    const float* v2  = (const float*)d_in[17];
    const float* Wt  = (const float*)d_in[18];
    const float* bt  = (const float*)d_in[19];
    const float* Wc  = (const float*)d_in[20];
    const float* bc  = (const float*)d_in[21];
    float* out = (float*)d_out;

    int N = in_sizes[0] / HD;        // nodes
    int E = in_sizes[1] / 2;         // edges
    int B = in_sizes[3] / HD;        // graphs
    int C = out_size / B;            // classes

    static const int MLP1_SMEM = (4096 + 4096 + 128 * 65 + 128) * (int)sizeof(float);
    static const int MLP2_SMEM = (4096 + 128 * 65 + 128) * (int)sizeof(float);
    cudaFuncSetAttribute(mlp1_kernel, cudaFuncAttributeMaxDynamicSharedMemorySize, MLP1_SMEM);
    cudaFuncSetAttribute(mlp2_kernel, cudaFuncAttributeMaxDynamicSharedMemorySize, MLP2_SMEM);

    hist_kernel<<<(E + 255) / 256, 256>>>(ei, E);

    int nb = (N + 1023) / 1024;
    scan_kernel<<<nb, 1024>>>(N);

    permute_kernel<<<(E + 255) / 256, 256>>>(ei, E);

    int mBlocks = (N + 127) / 128;
    mlp1_kernel<<<mBlocks, 512, MLP1_SMEM>>>(x, W1a, b1a, g1, be1, m1, v1, W1b, b1b, N);
    mlp2_kernel<<<mBlocks, 512, MLP2_SMEM>>>(W2, b2, g2, be2, m2, v2, batch, N);

    final_kernel<<<B, 64>>>(topo, Wt, bt, Wc, bc, out, B, C, N);
}

// round 7
// speedup vs baseline: 1.0584x; 1.0584x over previous
#include <cuda_runtime.h>
#include <math.h>

#define HD 64
#define MAXN 100000
#define MAXE 1200000
#define MAXB 1000
#define BN_EPS 1e-5f
#define STAGE_CAP 2048

typedef unsigned long long u64;

// Scratch (__device__ globals; zero-initialized at load, re-zeroed at the END
// of every launch by final_kernel so replays are deterministic)
__device__ float g_h[MAXN * HD];
__device__ float g_pool[MAXB * HD];
__device__ int   g_deg[MAXN];
__device__ int2  g_row2[MAXN];     // {rowptr, deg}
__device__ int   g_cursor[MAXN];
__device__ int   g_csr[MAXE];
__device__ u64   g_state[128];     // decoupled-lookback scan states

#define FLAG_AGG (1ull << 62)
#define FLAG_PRE (2ull << 62)

__device__ __forceinline__ void red_add_f4(float* p, float4 v) {
    asm volatile("red.global.add.v4.f32 [%0], {%1, %2, %3, %4};"
                 :: "l"(p), "f"(v.x), "f"(v.y), "f"(v.z), "f"(v.w)
                 : "memory");
}
__device__ __forceinline__ void red_add_i(int* p, int v) {
    asm volatile("red.global.add.s32 [%0], %1;" :: "l"(p), "r"(v) : "memory");
}
__device__ __forceinline__ u64 pack2(float x, float y) {
    u64 r; asm("mov.b64 %0, {%1, %2};" : "=l"(r) : "f"(x), "f"(y)); return r;
}
__device__ __forceinline__ float2 unpack2(u64 v) {
    float2 f; asm("mov.b64 {%0, %1}, %2;" : "=f"(f.x), "=f"(f.y) : "l"(v)); return f;
}
__device__ __forceinline__ void ffma2(u64& d, u64 a, u64 b) {
    asm("fma.rn.f32x2 %0, %1, %2, %0;" : "+l"(d) : "l"(a), "l"(b));
}

// ---------------------------------------------------------------------------
// K1: histogram of dst (deg zeroed by previous launch / initial state)
// ---------------------------------------------------------------------------
__global__ void hist_kernel(const int* __restrict__ ei, int E) {
    int t = blockIdx.x * blockDim.x + threadIdx.x;
    int nv = E >> 2;
    if (t < nv) {
        int4 d = ((const int4*)(ei + E))[t];
        red_add_i(&g_deg[d.x], 1);
        red_add_i(&g_deg[d.y], 1);
        red_add_i(&g_deg[d.z], 1);
        red_add_i(&g_deg[d.w], 1);
    }
    if (t == 0) for (int e = nv * 4; e < E; e++) red_add_i(&g_deg[ei[E + e]], 1);
}

// ---------------------------------------------------------------------------
// K2: single-pass exclusive scan (decoupled lookback), emits row2 + cursor
// ---------------------------------------------------------------------------
__global__ __launch_bounds__(1024) void scan_kernel(int N) {
    int b = blockIdx.x;
    int tid = threadIdx.x;
    int i = b * 1024 + tid;
    int v = (i < N) ? g_deg[i] : 0;
    int x = v;
    #pragma unroll
    for (int o = 1; o < 32; o <<= 1) {
        int y = __shfl_up_sync(0xFFFFFFFFu, x, o);
        if ((tid & 31) >= o) x += y;
    }
    __shared__ int ws[32];
    __shared__ int s_agg;
    __shared__ int s_excl;
    if ((tid & 31) == 31) ws[tid >> 5] = x;
    __syncthreads();
    if (tid < 32) {
        int y = ws[tid];
        #pragma unroll
        for (int o = 1; o < 32; o <<= 1) {
            int z = __shfl_up_sync(0xFFFFFFFFu, y, o);
            if (tid >= o) y += z;
        }
        ws[tid] = y;
    }
    __syncthreads();
    int base = (tid >= 32) ? ws[(tid >> 5) - 1] : 0;
    int incl = x + base;
    if (tid == 1023) s_agg = incl;
    __syncthreads();
    int agg = s_agg;

    if (tid < 32) {
        if (tid == 0) {
            u64 st = (b == 0 ? FLAG_PRE : FLAG_AGG) | (unsigned)agg;
            atomicExch(&g_state[b], st);
        }
        int excl = 0;
        if (b > 0) {
            int j = b - 1;
            bool done = false;
            while (!done) {
                int idx = j - tid;
                u64 s;
                if (idx >= 0) s = *(volatile u64*)&g_state[idx];
                else          s = FLAG_PRE;
                unsigned flag = (unsigned)(s >> 62);
                int val = (int)(unsigned)(s & 0xFFFFFFFFull);
                unsigned pmask = __ballot_sync(0xFFFFFFFFu, flag == 2u);
                unsigned rmask = __ballot_sync(0xFFFFFFFFu, flag >= 1u);
                if (pmask) {
                    int lead = __ffs(pmask) - 1;
                    unsigned need = (lead == 31) ? 0xFFFFFFFFu : ((1u << (lead + 1)) - 1u);
                    if ((rmask & need) == need) {
                        int contrib = (tid <= lead) ? val : 0;
                        #pragma unroll
                        for (int o = 16; o; o >>= 1)
                            contrib += __shfl_down_sync(0xFFFFFFFFu, contrib, o);
                        excl += __shfl_sync(0xFFFFFFFFu, contrib, 0);
                        done = true;
                    }
                } else if (rmask == 0xFFFFFFFFu) {
                    int contrib = val;
                    #pragma unroll
                    for (int o = 16; o; o >>= 1)
                        contrib += __shfl_down_sync(0xFFFFFFFFu, contrib, o);
                    excl += __shfl_sync(0xFFFFFFFFu, contrib, 0);
                    j -= 32;
                }
            }
            if (tid == 0)
                atomicExch(&g_state[b], FLAG_PRE | (unsigned)(excl + agg));
        }
        if (tid == 0) s_excl = excl;
    }
    __syncthreads();
    int rowp = s_excl + incl - v;
    if (i < N) {
        g_row2[i] = make_int2(rowp, v);
        g_cursor[i] = rowp;
    }
}

// ---------------------------------------------------------------------------
// K3: bucket edges by dst: csr[pos] = src. 4 edges/thread, atomics in flight.
// ---------------------------------------------------------------------------
__global__ void permute_kernel(const int* __restrict__ ei, int E) {
    int t = blockIdx.x * blockDim.x + threadIdx.x;
    int nv = E >> 2;
    if (t < nv) {
        int4 s = ((const int4*)ei)[t];
        int4 d = ((const int4*)(ei + E))[t];
        int p0 = atomicAdd(&g_cursor[d.x], 1);
        int p1 = atomicAdd(&g_cursor[d.y], 1);
        int p2 = atomicAdd(&g_cursor[d.z], 1);
        int p3 = atomicAdd(&g_cursor[d.w], 1);
        g_csr[p0] = s.x; g_csr[p1] = s.y; g_csr[p2] = s.z; g_csr[p3] = s.w;
    }
    if (t == 0) {
        for (int e = nv * 4; e < E; e++) {
            int p = atomicAdd(&g_cursor[ei[E + e]], 1);
            g_csr[p] = ei[e];
        }
    }
}

// ---------------------------------------------------------------------------
// Gather: 64 rows/block, 256 threads. Thread owns chunk c = tid&15 of rows
// rg, rg+16, rg+32, rg+48 (rg = tid>>4) and walks the 4 neighbor lists in
// lockstep, 2 neighbors per row per iteration => up to 8 LDGs in flight.
// ---------------------------------------------------------------------------
__device__ __forceinline__ float4 ldf4(const float* __restrict__ src, int n, int c) {
    return ((const float4*)src)[n * 16 + c];
}

__device__ __forceinline__ void gather64(const float* __restrict__ src,
                                         float* tile, int* sidx,
                                         int rowBase, int N, int tid) {
    int rend = min(rowBase + 63, N - 1);
    int2 first = g_row2[rowBase];
    int2 last  = g_row2[rend];
    int segStart = first.x;
    int segLen = last.x + last.y - segStart;
    int stage = min(segLen, STAGE_CAP);
    for (int i = tid; i < stage; i += 256) sidx[i] = g_csr[segStart + i];
    __syncthreads();

    int c = tid & 15;
    int rg = tid >> 4;

    float4 acc[4];
    int j[4], e[4], eS[4];
    #pragma unroll
    for (int i = 0; i < 4; i++) {
        int g = rowBase + rg + i * 16;
        if (g < N) {
            acc[i] = ldf4(src, g, c);
            int2 rd = g_row2[g];
            j[i] = rd.x - segStart;
            e[i] = j[i] + rd.y;
            eS[i] = min(e[i], stage);
        } else {
            acc[i] = make_float4(0.f, 0.f, 0.f, 0.f);
            j[i] = 0; e[i] = 0; eS[i] = 0;
        }
    }

    for (;;) {
        bool any = (j[0] < eS[0]) | (j[1] < eS[1]) | (j[2] < eS[2]) | (j[3] < eS[3]);
        if (!any) break;
        float4 v0[4], v1[4];
        #pragma unroll
        for (int i = 0; i < 4; i++) {
            v0[i] = make_float4(0.f, 0.f, 0.f, 0.f);
            v1[i] = make_float4(0.f, 0.f, 0.f, 0.f);
            if (j[i] < eS[i])     v0[i] = ldf4(src, sidx[j[i]], c);
            if (j[i] + 1 < eS[i]) v1[i] = ldf4(src, sidx[j[i] + 1], c);
        }
        #pragma unroll
        for (int i = 0; i < 4; i++) {
            acc[i].x += v0[i].x + v1[i].x;
            acc[i].y += v0[i].y + v1[i].y;
            acc[i].z += v0[i].z + v1[i].z;
            acc[i].w += v0[i].w + v1[i].w;
            j[i] += 2;
        }
    }
    // stage-cap overflow (rare)
    #pragma unroll
    for (int i = 0; i < 4; i++) {
        for (int t = eS[i]; t < e[i]; t++) {
            float4 v = ldf4(src, g_csr[segStart + t], c);
            acc[i].x += v.x; acc[i].y += v.y; acc[i].z += v.z; acc[i].w += v.w;
        }
    }
    #pragma unroll
    for (int i = 0; i < 4; i++) {
        float* tp = tile + (rg + i * 16) * 65 + c * 4;
        tp[0] = acc[i].x; tp[1] = acc[i].y; tp[2] = acc[i].z; tp[3] = acc[i].w;
    }
}

// One-row GEMM: acc[8] (u64 = 2 floats) += tile[rp,:] @ W[:, colBase..+15]
__device__ __forceinline__ void gemm_row(u64* acc, const float* tile, const float* W,
                                         int rp, int colBase) {
    #pragma unroll
    for (int k = 0; k < 64; k++) {
        float a = tile[rp * 65 + k];
        u64 A = pack2(a, a);
        const ulonglong2* w = (const ulonglong2*)(W + k * 64 + colBase);
        #pragma unroll
        for (int j2 = 0; j2 < 4; j2++) {
            ulonglong2 ww = w[j2];
            ffma2(acc[j2 * 2],     A, ww.x);
            ffma2(acc[j2 * 2 + 1], A, ww.y);
        }
    }
}

extern __shared__ float sdyn[];

// ---------------------------------------------------------------------------
// K4: mlp1: gather(x) -> GEMM(W1a)+BN+ReLU -> GEMM(W1b)+ReLU -> g_h
// 256 threads, 64 rows. sidx overlays Wb; W1b loaded after the gather.
// ---------------------------------------------------------------------------
__global__ __launch_bounds__(256) void mlp1_kernel(
    const float* __restrict__ x,
    const float* __restrict__ W1a, const float* __restrict__ b1a,
    const float* __restrict__ g1,  const float* __restrict__ be1,
    const float* __restrict__ m1,  const float* __restrict__ v1,
    const float* __restrict__ W1b, const float* __restrict__ b1b,
    int N) {
    float* Wa   = sdyn;                 // 4096
    float* Wb   = sdyn + 4096;          // 4096 (sidx overlay during gather)
    float* tile = sdyn + 8192;          // 64*65
    float* s1   = tile + 64 * 65;       // 64
    float* t1   = s1 + 64;              // 64
    int* sidx   = (int*)Wb;

    int tid = threadIdx.x;
    #pragma unroll
    for (int i = 0; i < 4; i++)
        ((float4*)Wa)[tid + 256 * i] = ((const float4*)W1a)[tid + 256 * i];
    if (tid < 64) {
        float s = g1[tid] * rsqrtf(v1[tid] + BN_EPS);
        s1[tid] = s;
        t1[tid] = be1[tid] - m1[tid] * s;
    }
    int rowBase = blockIdx.x * 64;
    gather64(x, tile, sidx, rowBase, N, tid);
    __syncthreads();   // sidx reads done

    // load W1b over sidx region; completes before GEMM2 (syncs below)
    #pragma unroll
    for (int i = 0; i < 4; i++)
        ((float4*)Wb)[tid + 256 * i] = ((const float4*)W1b)[tid + 256 * i];

    int rp = tid >> 2, q = tid & 3, colBase = q * 16;

    u64 acc[8];
    #pragma unroll
    for (int j = 0; j < 8; j++)
        acc[j] = pack2(b1a[colBase + 2 * j], b1a[colBase + 2 * j + 1]);
    gemm_row(acc, tile, Wa, rp, colBase);
    __syncthreads();   // tile reads + Wb stores complete

    #pragma unroll
    for (int j = 0; j < 8; j++) {
        int c0 = colBase + 2 * j;
        float2 p = unpack2(acc[j]);
        tile[rp * 65 + c0]     = fmaxf(p.x * s1[c0]     + t1[c0],     0.f);
        tile[rp * 65 + c0 + 1] = fmaxf(p.y * s1[c0 + 1] + t1[c0 + 1], 0.f);
    }
    __syncthreads();

    #pragma unroll
    for (int j = 0; j < 8; j++)
        acc[j] = pack2(b1b[colBase + 2 * j], b1b[colBase + 2 * j + 1]);
    gemm_row(acc, tile, Wb, rp, colBase);

    int gr = rowBase + rp;
    if (gr < N) {
        #pragma unroll
        for (int j4 = 0; j4 < 4; j4++) {
            float2 pa = unpack2(acc[j4 * 2]), pb = unpack2(acc[j4 * 2 + 1]);
            float4 y = make_float4(fmaxf(pa.x, 0.f), fmaxf(pa.y, 0.f),
                                   fmaxf(pb.x, 0.f), fmaxf(pb.y, 0.f));
            ((float4*)(g_h + gr * HD + colBase))[j4] = y;
        }
    }
}

// ---------------------------------------------------------------------------
// K5: mlp2: gather(h) -> GEMM(W2)+BN+ReLU -> pool[batch] += (REDG.128)
// ---------------------------------------------------------------------------
__global__ __launch_bounds__(256) void mlp2_kernel(
    const float* __restrict__ W2, const float* __restrict__ b2,
    const float* __restrict__ g2, const float* __restrict__ be2,
    const float* __restrict__ m2, const float* __restrict__ v2,
    const int* __restrict__ batch, int N) {
    float* Wa   = sdyn;                 // 4096 (sidx overlay during gather)
    float* tile = sdyn + 4096;          // 64*65
    float* s1   = tile + 64 * 65;       // 64
    float* t1   = s1 + 64;              // 64
    int* sidx   = (int*)Wa;

    int tid = threadIdx.x;
    if (tid < 64) {
        float s = g2[tid] * rsqrtf(v2[tid] + BN_EPS);
        s1[tid] = s;
        t1[tid] = be2[tid] - m2[tid] * s;
    }
    int rowBase = blockIdx.x * 64;
    gather64(g_h, tile, sidx, rowBase, N, tid);
    __syncthreads();

    #pragma unroll
    for (int i = 0; i < 4; i++)
        ((float4*)Wa)[tid + 256 * i] = ((const float4*)W2)[tid + 256 * i];
    __syncthreads();

    int rp = tid >> 2, q = tid & 3, colBase = q * 16;

    u64 acc[8];
    #pragma unroll
    for (int j = 0; j < 8; j++)
        acc[j] = pack2(b2[colBase + 2 * j], b2[colBase + 2 * j + 1]);
    gemm_row(acc, tile, Wa, rp, colBase);

    int gr = rowBase + rp;
    if (gr < N) {
        int b = batch[gr];
        float* pp = g_pool + b * HD + colBase;
        #pragma unroll
        for (int j4 = 0; j4 < 4; j4++) {
            int c0 = colBase + j4 * 4;
            float2 pa = unpack2(acc[j4 * 2]), pb = unpack2(acc[j4 * 2 + 1]);
            float4 y = make_float4(
                fmaxf(pa.x * s1[c0]     + t1[c0],     0.f),
                fmaxf(pa.y * s1[c0 + 1] + t1[c0 + 1], 0.f),
                fmaxf(pb.x * s1[c0 + 2] + t1[c0 + 2], 0.f),
                fmaxf(pb.y * s1[c0 + 3] + t1[c0 + 3], 0.f));
            red_add_f4(pp + j4 * 4, y);
        }
    }
}

// ---------------------------------------------------------------------------
// K6: per graph: xt = relu(topo@Wt+bt); out = [pool, xt] @ Wc + bc
// Also: cleanup for next replay (zero deg/state and pool-after-read).
// ---------------------------------------------------------------------------
__global__ void final_kernel(const float* __restrict__ topo,
                             const float* __restrict__ Wt, const float* __restrict__ bt,
                             const float* __restrict__ Wc, const float* __restrict__ bc,
                             float* __restrict__ out, int B, int C, int N) {
    int b = blockIdx.x;
    int t = threadIdx.x;   // 64
    __shared__ float comb[128];

    float acc = bt[t];
    #pragma unroll
    for (int k = 0; k < 64; k++)
        acc += topo[b * 64 + k] * Wt[k * 64 + t];
    comb[64 + t] = fmaxf(acc, 0.f);
    comb[t] = g_pool[b * HD + t];
    __syncthreads();

    if (t < C) {
        float o = bc[t];
        #pragma unroll
        for (int k = 0; k < 128; k++)
            o += comb[k] * Wc[k * C + t];
        out[b * C + t] = o;
    }

    // cleanup for next replay
    g_pool[b * HD + t] = 0.f;                 // read above (pre-sync), safe
    int gidx = b * 64 + t;
    for (int i = gidx; i < N; i += B * 64) g_deg[i] = 0;
    if (gidx < 128) g_state[gidx] = 0ull;
}

// ---------------------------------------------------------------------------
extern "C" void kernel_launch(void* const* d_in, const int* in_sizes, int n_in,
                              void* d_out, int out_size) {
    const float* x     = (const float*)d_in[0];
    const int*   ei    = (const int*)  d_in[1];
    const int*   batch = (const int*)  d_in[2];
    const float* topo  = (const float*)d_in[3];
    const float* W1a = (const float*)d_in[4];
    const float* b1a = (const float*)d_in[5];
    const float* g1  = (const float*)d_in[6];
    const float* be1 = (const float*)d_in[7];
    const float* m1  = (const float*)d_in[8];
    const float* v1  = (const float*)d_in[9];
    const float* W1b = (const float*)d_in[10];
    const float* b1b = (const float*)d_in[11];
    const float* W2  = (const float*)d_in[12];
    const float* b2  = (const float*)d_in[13];
    const float* g2  = (const float*)d_in[14];
    const float* be2 = (const float*)d_in[15];
    const float* m2  = (const float*)d_in[16];
    const float* v2  = (const float*)d_in[17];
    const float* Wt  = (const float*)d_in[18];
    const float* bt  = (const float*)d_in[19];
    const float* Wc  = (const float*)d_in[20];
    const float* bc  = (const float*)d_in[21];
    float* out = (float*)d_out;

    int N = in_sizes[0] / HD;        // nodes
    int E = in_sizes[1] / 2;         // edges
    int B = in_sizes[3] / HD;        // graphs
    int C = out_size / B;            // classes

    static const int MLP1_SMEM = (4096 + 4096 + 64 * 65 + 128) * (int)sizeof(float);
    static const int MLP2_SMEM = (4096 + 64 * 65 + 128) * (int)sizeof(float);
    cudaFuncSetAttribute(mlp1_kernel, cudaFuncAttributeMaxDynamicSharedMemorySize, MLP1_SMEM);
    cudaFuncSetAttribute(mlp2_kernel, cudaFuncAttributeMaxDynamicSharedMemorySize, MLP2_SMEM);

    int nv4 = (E >> 2);
    hist_kernel<<<(nv4 + 255) / 256, 256>>>(ei, E);

    int nb = (N + 1023) / 1024;
    scan_kernel<<<nb, 1024>>>(N);

    permute_kernel<<<(nv4 + 255) / 256, 256>>>(ei, E);

    int mBlocks = (N + 63) / 64;
    mlp1_kernel<<<mBlocks, 256, MLP1_SMEM>>>(x, W1a, b1a, g1, be1, m1, v1, W1b, b1b, N);
    mlp2_kernel<<<mBlocks, 256, MLP2_SMEM>>>(W2, b2, g2, be2, m2, v2, batch, N);

    final_kernel<<<B, 64>>>(topo, Wt, bt, Wc, bc, out, B, C, N);
}

// round 8
// speedup vs baseline: 1.0594x; 1.0009x over previous
#include <cuda_runtime.h>
#include <math.h>

#define HD 64
#define MAXN 100000
#define MAXE 1200000
#define MAXB 1000
#define BN_EPS 1e-5f
#define STAGE_CAP 2048

typedef unsigned long long u64;

// Scratch (__device__ globals; zero-initialized at load, re-zeroed at the END
// of every launch by final_kernel so replays are deterministic)
__device__ float g_h[MAXN * HD];
__device__ float g_pool[MAXB * HD];
__device__ int   g_deg[MAXN];
__device__ int2  g_row2[MAXN];     // {rowptr, deg}
__device__ int   g_cursor[MAXN];
__device__ int   g_csr[MAXE];
__device__ u64   g_state[128];     // decoupled-lookback scan states

#define FLAG_AGG (1ull << 62)
#define FLAG_PRE (2ull << 62)

__device__ __forceinline__ void red_add_f4(float* p, float4 v) {
    asm volatile("red.global.add.v4.f32 [%0], {%1, %2, %3, %4};"
                 :: "l"(p), "f"(v.x), "f"(v.y), "f"(v.z), "f"(v.w)
                 : "memory");
}
__device__ __forceinline__ void red_add_i(int* p, int v) {
    asm volatile("red.global.add.s32 [%0], %1;" :: "l"(p), "r"(v) : "memory");
}
__device__ __forceinline__ u64 pack2(float x, float y) {
    u64 r; asm("mov.b64 %0, {%1, %2};" : "=l"(r) : "f"(x), "f"(y)); return r;
}
__device__ __forceinline__ float2 unpack2(u64 v) {
    float2 f; asm("mov.b64 {%0, %1}, %2;" : "=f"(f.x), "=f"(f.y) : "l"(v)); return f;
}
__device__ __forceinline__ void ffma2(u64& d, u64 a, u64 b) {
    asm("fma.rn.f32x2 %0, %1, %2, %0;" : "+l"(d) : "l"(a), "l"(b));
}

// ---------------------------------------------------------------------------
// K1: histogram of dst (deg zeroed by previous launch / initial state)
// ---------------------------------------------------------------------------
__global__ void hist_kernel(const int* __restrict__ ei, int E) {
    int t = blockIdx.x * blockDim.x + threadIdx.x;
    int nv = E >> 2;
    if (t < nv) {
        int4 d = ((const int4*)(ei + E))[t];
        red_add_i(&g_deg[d.x], 1);
        red_add_i(&g_deg[d.y], 1);
        red_add_i(&g_deg[d.z], 1);
        red_add_i(&g_deg[d.w], 1);
    }
    if (t == 0) for (int e = nv * 4; e < E; e++) red_add_i(&g_deg[ei[E + e]], 1);
}

// ---------------------------------------------------------------------------
// K2: single-pass exclusive scan (decoupled lookback), emits row2 + cursor
// ---------------------------------------------------------------------------
__global__ __launch_bounds__(1024) void scan_kernel(int N) {
    int b = blockIdx.x;
    int tid = threadIdx.x;
    int i = b * 1024 + tid;
    int v = (i < N) ? g_deg[i] : 0;
    int x = v;
    #pragma unroll
    for (int o = 1; o < 32; o <<= 1) {
        int y = __shfl_up_sync(0xFFFFFFFFu, x, o);
        if ((tid & 31) >= o) x += y;
    }
    __shared__ int ws[32];
    __shared__ int s_agg;
    __shared__ int s_excl;
    if ((tid & 31) == 31) ws[tid >> 5] = x;
    __syncthreads();
    if (tid < 32) {
        int y = ws[tid];
        #pragma unroll
        for (int o = 1; o < 32; o <<= 1) {
            int z = __shfl_up_sync(0xFFFFFFFFu, y, o);
            if (tid >= o) y += z;
        }
        ws[tid] = y;
    }
    __syncthreads();
    int base = (tid >= 32) ? ws[(tid >> 5) - 1] : 0;
    int incl = x + base;
    if (tid == 1023) s_agg = incl;
    __syncthreads();
    int agg = s_agg;

    if (tid < 32) {
        if (tid == 0) {
            u64 st = (b == 0 ? FLAG_PRE : FLAG_AGG) | (unsigned)agg;
            atomicExch(&g_state[b], st);
        }
        int excl = 0;
        if (b > 0) {
            int j = b - 1;
            bool done = false;
            while (!done) {
                int idx = j - tid;
                u64 s;
                if (idx >= 0) s = *(volatile u64*)&g_state[idx];
                else          s = FLAG_PRE;
                unsigned flag = (unsigned)(s >> 62);
                int val = (int)(unsigned)(s & 0xFFFFFFFFull);
                unsigned pmask = __ballot_sync(0xFFFFFFFFu, flag == 2u);
                unsigned rmask = __ballot_sync(0xFFFFFFFFu, flag >= 1u);
                if (pmask) {
                    int lead = __ffs(pmask) - 1;
                    unsigned need = (lead == 31) ? 0xFFFFFFFFu : ((1u << (lead + 1)) - 1u);
                    if ((rmask & need) == need) {
                        int contrib = (tid <= lead) ? val : 0;
                        #pragma unroll
                        for (int o = 16; o; o >>= 1)
                            contrib += __shfl_down_sync(0xFFFFFFFFu, contrib, o);
                        excl += __shfl_sync(0xFFFFFFFFu, contrib, 0);
                        done = true;
                    }
                } else if (rmask == 0xFFFFFFFFu) {
                    int contrib = val;
                    #pragma unroll
                    for (int o = 16; o; o >>= 1)
                        contrib += __shfl_down_sync(0xFFFFFFFFu, contrib, o);
                    excl += __shfl_sync(0xFFFFFFFFu, contrib, 0);
                    j -= 32;
                }
            }
            if (tid == 0)
                atomicExch(&g_state[b], FLAG_PRE | (unsigned)(excl + agg));
        }
        if (tid == 0) s_excl = excl;
    }
    __syncthreads();
    int rowp = s_excl + incl - v;
    if (i < N) {
        g_row2[i] = make_int2(rowp, v);
        g_cursor[i] = rowp;
    }
}

// ---------------------------------------------------------------------------
// K3: bucket edges by dst: csr[pos] = src. 4 edges/thread, atomics in flight.
// ---------------------------------------------------------------------------
__global__ void permute_kernel(const int* __restrict__ ei, int E) {
    int t = blockIdx.x * blockDim.x + threadIdx.x;
    int nv = E >> 2;
    if (t < nv) {
        int4 s = ((const int4*)ei)[t];
        int4 d = ((const int4*)(ei + E))[t];
        int p0 = atomicAdd(&g_cursor[d.x], 1);
        int p1 = atomicAdd(&g_cursor[d.y], 1);
        int p2 = atomicAdd(&g_cursor[d.z], 1);
        int p3 = atomicAdd(&g_cursor[d.w], 1);
        g_csr[p0] = s.x; g_csr[p1] = s.y; g_csr[p2] = s.z; g_csr[p3] = s.w;
    }
    if (t == 0) {
        for (int e = nv * 4; e < E; e++) {
            int p = atomicAdd(&g_cursor[ei[E + e]], 1);
            g_csr[p] = ei[e];
        }
    }
}

// ---------------------------------------------------------------------------
// Gather: warp-per-row, lane-parallel neighbors. 64 rows/block, 256 threads.
// One warp handles 8 rows sequentially. Per loop iteration the warp loads
// 4 neighbor rows: lanes 0-15 cover neighbors n0/n2 (chunk = lane&15),
// lanes 16-31 cover n1/n3. Final shfl_xor(16) folds the halves.
// Live state per thread: 1 float4 accumulator + 2 float4 temps (~28 regs).
// ---------------------------------------------------------------------------
__device__ __forceinline__ float4 ldf4(const float* __restrict__ src, int n, int c) {
    return ((const float4*)src)[n * 16 + c];
}

__device__ __forceinline__ void gather64w(const float* __restrict__ src,
                                          float* tile, int* sidx,
                                          int rowBase, int N, int tid) {
    int rend = min(rowBase + 63, N - 1);
    int2 first = g_row2[rowBase];
    int2 last  = g_row2[rend];
    int segStart = first.x;
    int segLen = last.x + last.y - segStart;
    int stage = min(segLen, STAGE_CAP);
    for (int i = tid; i < stage; i += 256) sidx[i] = g_csr[segStart + i];
    __syncthreads();

    int wid  = tid >> 5;
    int lane = tid & 31;
    int half = lane >> 4;      // 0: even-index neighbor, 1: odd-index neighbor
    int c    = lane & 15;      // float4 chunk within the 64-float row

    #pragma unroll 1
    for (int s = 0; s < 8; s++) {
        int g = rowBase + wid * 8 + s;
        if (g >= N) break;                       // uniform within warp
        int2 rd = g_row2[g];
        int j0 = rd.x - segStart;
        int d  = rd.y;
        int dS = min(d, stage - j0);             // staged portion

        float4 acc = make_float4(0.f, 0.f, 0.f, 0.f);
        if (half == 0) acc = ldf4(src, g, c);    // self term (lanes 0-15)

        int t = 0;
        // 4 neighbors per iteration: 2 warp-wide LDG.128 (1KB in flight)
        for (; t + 4 <= dS; t += 4) {
            int na = sidx[j0 + t + half];
            int nb = sidx[j0 + t + 2 + half];
            float4 va = ldf4(src, na, c);
            float4 vb = ldf4(src, nb, c);
            acc.x += va.x + vb.x;
            acc.y += va.y + vb.y;
            acc.z += va.z + vb.z;
            acc.w += va.w + vb.w;
        }
        // remainder (0..3 neighbors), 2 at a time with guard
        for (; t < dS; t += 2) {
            int idx = t + half;
            if (idx < dS) {
                float4 v = ldf4(src, sidx[j0 + idx], c);
                acc.x += v.x; acc.y += v.y; acc.z += v.z; acc.w += v.w;
            }
        }
        // stage-cap overflow (rare): read indices straight from g_csr
        for (int u = dS; u < d; u += 2) {
            int idx = u + half;
            if (idx < d) {
                float4 v = ldf4(src, g_csr[rd.x + idx], c);
                acc.x += v.x; acc.y += v.y; acc.z += v.z; acc.w += v.w;
            }
        }
        // fold odd-half into even-half
        acc.x += __shfl_xor_sync(0xFFFFFFFFu, acc.x, 16);
        acc.y += __shfl_xor_sync(0xFFFFFFFFu, acc.y, 16);
        acc.z += __shfl_xor_sync(0xFFFFFFFFu, acc.z, 16);
        acc.w += __shfl_xor_sync(0xFFFFFFFFu, acc.w, 16);
        if (half == 0) {
            float* tp = tile + (wid * 8 + s) * 65 + c * 4;
            tp[0] = acc.x; tp[1] = acc.y; tp[2] = acc.z; tp[3] = acc.w;
        }
    }
}

// One-row GEMM: acc[8] (u64 = 2 floats) += tile[rp,:] @ W[:, colBase..+15]
__device__ __forceinline__ void gemm_row(u64* acc, const float* tile, const float* W,
                                         int rp, int colBase) {
    #pragma unroll
    for (int k = 0; k < 64; k++) {
        float a = tile[rp * 65 + k];
        u64 A = pack2(a, a);
        const ulonglong2* w = (const ulonglong2*)(W + k * 64 + colBase);
        #pragma unroll
        for (int j2 = 0; j2 < 4; j2++) {
            ulonglong2 ww = w[j2];
            ffma2(acc[j2 * 2],     A, ww.x);
            ffma2(acc[j2 * 2 + 1], A, ww.y);
        }
    }
}

extern __shared__ float sdyn[];

// ---------------------------------------------------------------------------
// K4: mlp1: gather(x) -> GEMM(W1a)+BN+ReLU -> GEMM(W1b)+ReLU -> g_h
// 256 threads, 64 rows. sidx overlays Wb; W1b loaded after the gather.
// ---------------------------------------------------------------------------
__global__ __launch_bounds__(256) void mlp1_kernel(
    const float* __restrict__ x,
    const float* __restrict__ W1a, const float* __restrict__ b1a,
    const float* __restrict__ g1,  const float* __restrict__ be1,
    const float* __restrict__ m1,  const float* __restrict__ v1,
    const float* __restrict__ W1b, const float* __restrict__ b1b,
    int N) {
    float* Wa   = sdyn;                 // 4096
    float* Wb   = sdyn + 4096;          // 4096 (sidx overlay during gather)
    float* tile = sdyn + 8192;          // 64*65
    float* s1   = tile + 64 * 65;       // 64
    float* t1   = s1 + 64;              // 64
    int* sidx   = (int*)Wb;

    int tid = threadIdx.x;
    #pragma unroll
    for (int i = 0; i < 4; i++)
        ((float4*)Wa)[tid + 256 * i] = ((const float4*)W1a)[tid + 256 * i];
    if (tid < 64) {
        float s = g1[tid] * rsqrtf(v1[tid] + BN_EPS);
        s1[tid] = s;
        t1[tid] = be1[tid] - m1[tid] * s;
    }
    int rowBase = blockIdx.x * 64;
    gather64w(x, tile, sidx, rowBase, N, tid);
    __syncthreads();   // sidx reads done

    // load W1b over sidx region; completes before GEMM2 (sync below)
    #pragma unroll
    for (int i = 0; i < 4; i++)
        ((float4*)Wb)[tid + 256 * i] = ((const float4*)W1b)[tid + 256 * i];

    int rp = tid >> 2, q = tid & 3, colBase = q * 16;

    u64 acc[8];
    #pragma unroll
    for (int j = 0; j < 8; j++)
        acc[j] = pack2(b1a[colBase + 2 * j], b1a[colBase + 2 * j + 1]);
    gemm_row(acc, tile, Wa, rp, colBase);
    __syncthreads();   // tile reads + Wb stores complete

    #pragma unroll
    for (int j = 0; j < 8; j++) {
        int c0 = colBase + 2 * j;
        float2 p = unpack2(acc[j]);
        tile[rp * 65 + c0]     = fmaxf(p.x * s1[c0]     + t1[c0],     0.f);
        tile[rp * 65 + c0 + 1] = fmaxf(p.y * s1[c0 + 1] + t1[c0 + 1], 0.f);
    }
    __syncthreads();

    #pragma unroll
    for (int j = 0; j < 8; j++)
        acc[j] = pack2(b1b[colBase + 2 * j], b1b[colBase + 2 * j + 1]);
    gemm_row(acc, tile, Wb, rp, colBase);

    int gr = rowBase + rp;
    if (gr < N) {
        #pragma unroll
        for (int j4 = 0; j4 < 4; j4++) {
            float2 pa = unpack2(acc[j4 * 2]), pb = unpack2(acc[j4 * 2 + 1]);
            float4 y = make_float4(fmaxf(pa.x, 0.f), fmaxf(pa.y, 0.f),
                                   fmaxf(pb.x, 0.f), fmaxf(pb.y, 0.f));
            ((float4*)(g_h + gr * HD + colBase))[j4] = y;
        }
    }
}

// ---------------------------------------------------------------------------
// K5: mlp2: gather(h) -> GEMM(W2)+BN+ReLU -> pool[batch] += (REDG.128)
// ---------------------------------------------------------------------------
__global__ __launch_bounds__(256) void mlp2_kernel(
    const float* __restrict__ W2, const float* __restrict__ b2,
    const float* __restrict__ g2, const float* __restrict__ be2,
    const float* __restrict__ m2, const float* __restrict__ v2,
    const int* __restrict__ batch, int N) {
    float* Wa   = sdyn;                 // 4096 (sidx overlay during gather)
    float* tile = sdyn + 4096;          // 64*65
    float* s1   = tile + 64 * 65;       // 64
    float* t1   = s1 + 64;              // 64
    int* sidx   = (int*)Wa;

    int tid = threadIdx.x;
    if (tid < 64) {
        float s = g2[tid] * rsqrtf(v2[tid] + BN_EPS);
        s1[tid] = s;
        t1[tid] = be2[tid] - m2[tid] * s;
    }
    int rowBase = blockIdx.x * 64;
    gather64w(g_h, tile, sidx, rowBase, N, tid);
    __syncthreads();

    #pragma unroll
    for (int i = 0; i < 4; i++)
        ((float4*)Wa)[tid + 256 * i] = ((const float4*)W2)[tid + 256 * i];
    __syncthreads();

    int rp = tid >> 2, q = tid & 3, colBase = q * 16;

    u64 acc[8];
    #pragma unroll
    for (int j = 0; j < 8; j++)
        acc[j] = pack2(b2[colBase + 2 * j], b2[colBase + 2 * j + 1]);
    gemm_row(acc, tile, Wa, rp, colBase);

    int gr = rowBase + rp;
    if (gr < N) {
        int b = batch[gr];
        float* pp = g_pool + b * HD + colBase;
        #pragma unroll
        for (int j4 = 0; j4 < 4; j4++) {
            int c0 = colBase + j4 * 4;
            float2 pa = unpack2(acc[j4 * 2]), pb = unpack2(acc[j4 * 2 + 1]);
            float4 y = make_float4(
                fmaxf(pa.x * s1[c0]     + t1[c0],     0.f),
                fmaxf(pa.y * s1[c0 + 1] + t1[c0 + 1], 0.f),
                fmaxf(pb.x * s1[c0 + 2] + t1[c0 + 2], 0.f),
                fmaxf(pb.y * s1[c0 + 3] + t1[c0 + 3], 0.f));
            red_add_f4(pp + j4 * 4, y);
        }
    }
}

// ---------------------------------------------------------------------------
// K6: per graph: xt = relu(topo@Wt+bt); out = [pool, xt] @ Wc + bc
// Also: cleanup for next replay (zero deg/state and pool-after-read).
// ---------------------------------------------------------------------------
__global__ void final_kernel(const float* __restrict__ topo,
                             const float* __restrict__ Wt, const float* __restrict__ bt,
                             const float* __restrict__ Wc, const float* __restrict__ bc,
                             float* __restrict__ out, int B, int C, int N) {
    int b = blockIdx.x;
    int t = threadIdx.x;   // 64
    __shared__ float comb[128];

    float acc = bt[t];
    #pragma unroll
    for (int k = 0; k < 64; k++)
        acc += topo[b * 64 + k] * Wt[k * 64 + t];
    comb[64 + t] = fmaxf(acc, 0.f);
    comb[t] = g_pool[b * HD + t];
    __syncthreads();

    if (t < C) {
        float o = bc[t];
        #pragma unroll
        for (int k = 0; k < 128; k++)
            o += comb[k] * Wc[k * C + t];
        out[b * C + t] = o;
    }

    // cleanup for next replay
    g_pool[b * HD + t] = 0.f;                 // read above (pre-sync), safe
    int gidx = b * 64 + t;
    for (int i = gidx; i < N; i += B * 64) g_deg[i] = 0;
    if (gidx < 128) g_state[gidx] = 0ull;
}

// ---------------------------------------------------------------------------
extern "C" void kernel_launch(void* const* d_in, const int* in_sizes, int n_in,
                              void* d_out, int out_size) {
    const float* x     = (const float*)d_in[0];
    const int*   ei    = (const int*)  d_in[1];
    const int*   batch = (const int*)  d_in[2];
    const float* topo  = (const float*)d_in[3];
    const float* W1a = (const float*)d_in[4];
    const float* b1a = (const float*)d_in[5];
    const float* g1  = (const float*)d_in[6];
    const float* be1 = (const float*)d_in[7];
    const float* m1  = (const float*)d_in[8];
    const float* v1  = (const float*)d_in[9];
    const float* W1b = (const float*)d_in[10];
    const float* b1b = (const float*)d_in[11];
    const float* W2  = (const float*)d_in[12];
    const float* b2  = (const float*)d_in[13];
    const float* g2  = (const float*)d_in[14];
    const float* be2 = (const float*)d_in[15];
    const float* m2  = (const float*)d_in[16];
    const float* v2  = (const float*)d_in[17];
    const float* Wt  = (const float*)d_in[18];
    const float* bt  = (const float*)d_in[19];
    const float* Wc  = (const float*)d_in[20];
    const float* bc  = (const float*)d_in[21];
    float* out = (float*)d_out;

    int N = in_sizes[0] / HD;        // nodes
    int E = in_sizes[1] / 2;         // edges
    int B = in_sizes[3] / HD;        // graphs
    int C = out_size / B;            // classes

    static const int MLP1_SMEM = (4096 + 4096 + 64 * 65 + 128) * (int)sizeof(float);
    static const int MLP2_SMEM = (4096 + 64 * 65 + 128) * (int)sizeof(float);
    cudaFuncSetAttribute(mlp1_kernel, cudaFuncAttributeMaxDynamicSharedMemorySize, MLP1_SMEM);
    cudaFuncSetAttribute(mlp2_kernel, cudaFuncAttributeMaxDynamicSharedMemorySize, MLP2_SMEM);

    int nv4 = (E >> 2);
    hist_kernel<<<(nv4 + 255) / 256, 256>>>(ei, E);

    int nb = (N + 1023) / 1024;
    scan_kernel<<<nb, 1024>>>(N);

    permute_kernel<<<(nv4 + 255) / 256, 256>>>(ei, E);

    int mBlocks = (N + 63) / 64;
    mlp1_kernel<<<mBlocks, 256, MLP1_SMEM>>>(x, W1a, b1a, g1, be1, m1, v1, W1b, b1b, N);
    mlp2_kernel<<<mBlocks, 256, MLP2_SMEM>>>(W2, b2, g2, be2, m2, v2, batch, N);

    final_kernel<<<B, 64>>>(topo, Wt, bt, Wc, bc, out, B, C, N);
}

// round 10
// speedup vs baseline: 2.0920x; 1.9748x over previous
#include <cuda_runtime.h>
#include <math.h>

#define HD 64
#define MAXN 100000
#define MAXE 1200000
#define MAXB 1000
#define BN_EPS 1e-5f

typedef unsigned long long u64;

// Scratch (__device__ globals; zero-initialized at load, re-zeroed at the END
// of every launch by final_kernel so replays are deterministic).
// NOTE: these are referenced ONLY from device code (host cannot take their address).
__device__ float g_agg[MAXN * HD];   // reused for both layers' aggregation
__device__ float g_h[MAXN * HD];
__device__ float g_pool[MAXB * HD];
__device__ int   g_deg[MAXN];
__device__ int2  g_row2[MAXN];       // {rowptr, deg}
__device__ int   g_cursor[MAXN];
__device__ int   g_csr[MAXE];
__device__ u64   g_state[128];       // decoupled-lookback scan states

#define FLAG_AGG (1ull << 62)
#define FLAG_PRE (2ull << 62)

__device__ __forceinline__ void red_add_f4(float* p, float4 v) {
    asm volatile("red.global.add.v4.f32 [%0], {%1, %2, %3, %4};"
                 :: "l"(p), "f"(v.x), "f"(v.y), "f"(v.z), "f"(v.w)
                 : "memory");
}
__device__ __forceinline__ void red_add_i(int* p, int v) {
    asm volatile("red.global.add.s32 [%0], %1;" :: "l"(p), "r"(v) : "memory");
}
__device__ __forceinline__ u64 pack2(float x, float y) {
    u64 r; asm("mov.b64 %0, {%1, %2};" : "=l"(r) : "f"(x), "f"(y)); return r;
}
__device__ __forceinline__ float2 unpack2(u64 v) {
    float2 f; asm("mov.b64 {%0, %1}, %2;" : "=f"(f.x), "=f"(f.y) : "l"(v)); return f;
}
__device__ __forceinline__ void ffma2(u64& d, u64 a, u64 b) {
    asm("fma.rn.f32x2 %0, %1, %2, %0;" : "+l"(d) : "l"(a), "l"(b));
}
__device__ __forceinline__ float4 ldf4(const float* __restrict__ src, int n, int c) {
    return ((const float4*)src)[n * 16 + c];
}

// ---------------------------------------------------------------------------
// K1: histogram of dst
// ---------------------------------------------------------------------------
__global__ void hist_kernel(const int* __restrict__ ei, int E) {
    int t = blockIdx.x * blockDim.x + threadIdx.x;
    int nv = E >> 2;
    if (t < nv) {
        int4 d = ((const int4*)(ei + E))[t];
        red_add_i(&g_deg[d.x], 1);
        red_add_i(&g_deg[d.y], 1);
        red_add_i(&g_deg[d.z], 1);
        red_add_i(&g_deg[d.w], 1);
    }
    if (t == 0) for (int e = nv * 4; e < E; e++) red_add_i(&g_deg[ei[E + e]], 1);
}

// ---------------------------------------------------------------------------
// K2: single-pass exclusive scan (decoupled lookback), emits row2 + cursor
// ---------------------------------------------------------------------------
__global__ __launch_bounds__(1024) void scan_kernel(int N) {
    int b = blockIdx.x;
    int tid = threadIdx.x;
    int i = b * 1024 + tid;
    int v = (i < N) ? g_deg[i] : 0;
    int x = v;
    #pragma unroll
    for (int o = 1; o < 32; o <<= 1) {
        int y = __shfl_up_sync(0xFFFFFFFFu, x, o);
        if ((tid & 31) >= o) x += y;
    }
    __shared__ int ws[32];
    __shared__ int s_agg;
    __shared__ int s_excl;
    if ((tid & 31) == 31) ws[tid >> 5] = x;
    __syncthreads();
    if (tid < 32) {
        int y = ws[tid];
        #pragma unroll
        for (int o = 1; o < 32; o <<= 1) {
            int z = __shfl_up_sync(0xFFFFFFFFu, y, o);
            if (tid >= o) y += z;
        }
        ws[tid] = y;
    }
    __syncthreads();
    int base = (tid >= 32) ? ws[(tid >> 5) - 1] : 0;
    int incl = x + base;
    if (tid == 1023) s_agg = incl;
    __syncthreads();
    int agg = s_agg;

    if (tid < 32) {
        if (tid == 0) {
            u64 st = (b == 0 ? FLAG_PRE : FLAG_AGG) | (unsigned)agg;
            atomicExch(&g_state[b], st);
        }
        int excl = 0;
        if (b > 0) {
            int j = b - 1;
            bool done = false;
            while (!done) {
                int idx = j - tid;
                u64 s;
                if (idx >= 0) s = *(volatile u64*)&g_state[idx];
                else          s = FLAG_PRE;
                unsigned flag = (unsigned)(s >> 62);
                int val = (int)(unsigned)(s & 0xFFFFFFFFull);
                unsigned pmask = __ballot_sync(0xFFFFFFFFu, flag == 2u);
                unsigned rmask = __ballot_sync(0xFFFFFFFFu, flag >= 1u);
                if (pmask) {
                    int lead = __ffs(pmask) - 1;
                    unsigned need = (lead == 31) ? 0xFFFFFFFFu : ((1u << (lead + 1)) - 1u);
                    if ((rmask & need) == need) {
                        int contrib = (tid <= lead) ? val : 0;
                        #pragma unroll
                        for (int o = 16; o; o >>= 1)
                            contrib += __shfl_down_sync(0xFFFFFFFFu, contrib, o);
                        excl += __shfl_sync(0xFFFFFFFFu, contrib, 0);
                        done = true;
                    }
                } else if (rmask == 0xFFFFFFFFu) {
                    int contrib = val;
                    #pragma unroll
                    for (int o = 16; o; o >>= 1)
                        contrib += __shfl_down_sync(0xFFFFFFFFu, contrib, o);
                    excl += __shfl_sync(0xFFFFFFFFu, contrib, 0);
                    j -= 32;
                }
            }
            if (tid == 0)
                atomicExch(&g_state[b], FLAG_PRE | (unsigned)(excl + agg));
        }
        if (tid == 0) s_excl = excl;
    }
    __syncthreads();
    int rowp = s_excl + incl - v;
    if (i < N) {
        g_row2[i] = make_int2(rowp, v);
        g_cursor[i] = rowp;
    }
}

// ---------------------------------------------------------------------------
// K3: bucket edges by dst: csr[pos] = src
// ---------------------------------------------------------------------------
__global__ void permute_kernel(const int* __restrict__ ei, int E) {
    int t = blockIdx.x * blockDim.x + threadIdx.x;
    int nv = E >> 2;
    if (t < nv) {
        int4 s = ((const int4*)ei)[t];
        int4 d = ((const int4*)(ei + E))[t];
        int p0 = atomicAdd(&g_cursor[d.x], 1);
        int p1 = atomicAdd(&g_cursor[d.y], 1);
        int p2 = atomicAdd(&g_cursor[d.z], 1);
        int p3 = atomicAdd(&g_cursor[d.w], 1);
        g_csr[p0] = s.x; g_csr[p1] = s.y; g_csr[p2] = s.z; g_csr[p3] = s.w;
    }
    if (t == 0) {
        for (int e = nv * 4; e < E; e++) {
            int p = atomicAdd(&g_cursor[ei[E + e]], 1);
            g_csr[p] = ei[e];
        }
    }
}

// ---------------------------------------------------------------------------
// K4/K6: aggregation, warp-per-row. mode 0: src = x (param) ; mode 1: src = g_h.
// dst is always g_agg (device-resolved; device globals never cross the launch ABI).
// Lanes 0-15: chunk c of even neighbors (+ self); lanes 16-31: odd neighbors.
// ---------------------------------------------------------------------------
__global__ __launch_bounds__(256) void agg_kernel(const float* __restrict__ x,
                                                  int mode, int N) {
    int w = (blockIdx.x * blockDim.x + threadIdx.x) >> 5;
    if (w >= N) return;
    const float* __restrict__ src = (mode == 0) ? x : (const float*)g_h;
    int lane = threadIdx.x & 31;
    int half = lane >> 4;
    int c    = lane & 15;

    int2 rd = g_row2[w];
    int j0 = rd.x, d = rd.y;

    float4 acc = make_float4(0.f, 0.f, 0.f, 0.f);
    if (half == 0) acc = ldf4(src, w, c);   // self term

    int t = 0;
    for (; t + 4 <= d; t += 4) {
        int na = g_csr[j0 + t + half];
        int nb = g_csr[j0 + t + 2 + half];
        float4 va = ldf4(src, na, c);
        float4 vb = ldf4(src, nb, c);
        acc.x += va.x + vb.x;
        acc.y += va.y + vb.y;
        acc.z += va.z + vb.z;
        acc.w += va.w + vb.w;
    }
    for (; t < d; t += 2) {
        int idx = t + half;
        if (idx < d) {
            float4 v = ldf4(src, g_csr[j0 + idx], c);
            acc.x += v.x; acc.y += v.y; acc.z += v.z; acc.w += v.w;
        }
    }
    acc.x += __shfl_xor_sync(0xFFFFFFFFu, acc.x, 16);
    acc.y += __shfl_xor_sync(0xFFFFFFFFu, acc.y, 16);
    acc.z += __shfl_xor_sync(0xFFFFFFFFu, acc.z, 16);
    acc.w += __shfl_xor_sync(0xFFFFFFFFu, acc.w, 16);
    if (half == 0) ((float4*)g_agg)[w * 16 + c] = acc;
}

// ---------------------------------------------------------------------------
// GEMM core: 128 threads, 128-row tile, 8 rows x 8 cols per thread.
// Weight smem: row stride 68; col block cb at offset cb*8 + (cb>>2)*4 -> the
// 8 LDS.64 per warp hit 8 distinct bank pairs (conflict-free).
// smem traffic: 8 A + 8 B words per 64 MACs = 1 B/MAC (was 4.25).
// ---------------------------------------------------------------------------
#define WSTRIDE 68
__device__ __forceinline__ int wswz(int k, int c) {
    int cb = c >> 3;
    return k * WSTRIDE + cb * 8 + ((cb >> 2) << 2) + (c & 7);
}

__device__ __forceinline__ void load_w(float* Wsw, const float* __restrict__ W, int tid) {
    for (int idx = tid; idx < 4096; idx += 128)
        Wsw[wswz(idx >> 6, idx & 63)] = W[idx];
}

__device__ __forceinline__ void gemm8x8(u64 acc[8][4], const float* tile,
                                        const float* Wsw, int rg, int cg) {
    const float* wb = Wsw + cg * 8 + ((cg >> 2) << 2);
    #pragma unroll 4
    for (int k = 0; k < 64; k++) {
        float a[8];
        #pragma unroll
        for (int i = 0; i < 8; i++) a[i] = tile[(rg * 8 + i) * 65 + k];
        u64 b[4];
        #pragma unroll
        for (int j = 0; j < 4; j++) b[j] = *(const u64*)(wb + k * WSTRIDE + 2 * j);
        #pragma unroll
        for (int i = 0; i < 8; i++) {
            u64 A = pack2(a[i], a[i]);
            #pragma unroll
            for (int j = 0; j < 4; j++) ffma2(acc[i][j], A, b[j]);
        }
    }
}

extern __shared__ float sdyn[];

// ---------------------------------------------------------------------------
// K5: mlp1: tile = g_agg[128 rows] -> GEMM(W1a)+BN+ReLU -> GEMM(W1b)+ReLU -> g_h
// ---------------------------------------------------------------------------
__global__ __launch_bounds__(128) void mlp1_kernel(
    const float* __restrict__ W1a, const float* __restrict__ b1a,
    const float* __restrict__ g1,  const float* __restrict__ be1,
    const float* __restrict__ m1,  const float* __restrict__ v1,
    const float* __restrict__ W1b, const float* __restrict__ b1b,
    int N) {
    float* Wa   = sdyn;                       // 64*68 = 4352
    float* Wb   = Wa + 64 * WSTRIDE;          // 4352
    float* tile = Wb + 64 * WSTRIDE;          // 128*65 = 8320
    float* s1   = tile + 128 * 65;            // 64
    float* t1   = s1 + 64;                    // 64

    int tid = threadIdx.x;
    load_w(Wa, W1a, tid);
    load_w(Wb, W1b, tid);
    if (tid < 64) {
        float s = g1[tid] * rsqrtf(v1[tid] + BN_EPS);
        s1[tid] = s;
        t1[tid] = be1[tid] - m1[tid] * s;
    }
    int rowBase = blockIdx.x * 128;
    for (int idx = tid; idx < 128 * 16; idx += 128) {
        int r = idx >> 4, c = idx & 15;
        int gr = rowBase + r;
        float4 v = (gr < N) ? ((const float4*)g_agg)[gr * 16 + c]
                            : make_float4(0.f, 0.f, 0.f, 0.f);
        float* tp = tile + r * 65 + c * 4;
        tp[0] = v.x; tp[1] = v.y; tp[2] = v.z; tp[3] = v.w;
    }
    __syncthreads();

    int rg = tid >> 3, cg = tid & 7;

    u64 acc[8][4];
    #pragma unroll
    for (int i = 0; i < 8; i++)
        #pragma unroll
        for (int j = 0; j < 4; j++)
            acc[i][j] = pack2(b1a[cg * 8 + 2 * j], b1a[cg * 8 + 2 * j + 1]);
    gemm8x8(acc, tile, Wa, rg, cg);
    __syncthreads();   // tile reads done before overwrite

    // BN + ReLU -> tile
    #pragma unroll
    for (int i = 0; i < 8; i++) {
        int r = rg * 8 + i;
        #pragma unroll
        for (int j = 0; j < 4; j++) {
            int c0 = cg * 8 + 2 * j;
            float2 p = unpack2(acc[i][j]);
            tile[r * 65 + c0]     = fmaxf(p.x * s1[c0]     + t1[c0],     0.f);
            tile[r * 65 + c0 + 1] = fmaxf(p.y * s1[c0 + 1] + t1[c0 + 1], 0.f);
        }
    }
    __syncthreads();

    #pragma unroll
    for (int i = 0; i < 8; i++)
        #pragma unroll
        for (int j = 0; j < 4; j++)
            acc[i][j] = pack2(b1b[cg * 8 + 2 * j], b1b[cg * 8 + 2 * j + 1]);
    gemm8x8(acc, tile, Wb, rg, cg);

    #pragma unroll
    for (int i = 0; i < 8; i++) {
        int gr = rowBase + rg * 8 + i;
        if (gr < N) {
            float2 p0 = unpack2(acc[i][0]), p1 = unpack2(acc[i][1]);
            float2 p2 = unpack2(acc[i][2]), p3 = unpack2(acc[i][3]);
            float4 ya = make_float4(fmaxf(p0.x, 0.f), fmaxf(p0.y, 0.f),
                                    fmaxf(p1.x, 0.f), fmaxf(p1.y, 0.f));
            float4 yb = make_float4(fmaxf(p2.x, 0.f), fmaxf(p2.y, 0.f),
                                    fmaxf(p3.x, 0.f), fmaxf(p3.y, 0.f));
            float4* op = (float4*)(g_h + gr * HD + cg * 8);
            op[0] = ya; op[1] = yb;
        }
    }
}

// ---------------------------------------------------------------------------
// K7: mlp2: tile = g_agg -> GEMM(W2)+BN+ReLU -> pool[batch] += (REDG.128)
// ---------------------------------------------------------------------------
__global__ __launch_bounds__(128) void mlp2_kernel(
    const float* __restrict__ W2, const float* __restrict__ b2,
    const float* __restrict__ g2, const float* __restrict__ be2,
    const float* __restrict__ m2, const float* __restrict__ v2,
    const int* __restrict__ batch, int N) {
    float* Wa   = sdyn;                       // 4352
    float* tile = Wa + 64 * WSTRIDE;          // 8320
    float* s1   = tile + 128 * 65;            // 64
    float* t1   = s1 + 64;                    // 64

    int tid = threadIdx.x;
    load_w(Wa, W2, tid);
    if (tid < 64) {
        float s = g2[tid] * rsqrtf(v2[tid] + BN_EPS);
        s1[tid] = s;
        t1[tid] = be2[tid] - m2[tid] * s;
    }
    int rowBase = blockIdx.x * 128;
    for (int idx = tid; idx < 128 * 16; idx += 128) {
        int r = idx >> 4, c = idx & 15;
        int gr = rowBase + r;
        float4 v = (gr < N) ? ((const float4*)g_agg)[gr * 16 + c]
                            : make_float4(0.f, 0.f, 0.f, 0.f);
        float* tp = tile + r * 65 + c * 4;
        tp[0] = v.x; tp[1] = v.y; tp[2] = v.z; tp[3] = v.w;
    }
    __syncthreads();

    int rg = tid >> 3, cg = tid & 7;

    u64 acc[8][4];
    #pragma unroll
    for (int i = 0; i < 8; i++)
        #pragma unroll
        for (int j = 0; j < 4; j++)
            acc[i][j] = pack2(b2[cg * 8 + 2 * j], b2[cg * 8 + 2 * j + 1]);
    gemm8x8(acc, tile, Wa, rg, cg);

    #pragma unroll
    for (int i = 0; i < 8; i++) {
        int gr = rowBase + rg * 8 + i;
        if (gr < N) {
            int b = batch[gr];
            float2 p0 = unpack2(acc[i][0]), p1 = unpack2(acc[i][1]);
            float2 p2 = unpack2(acc[i][2]), p3 = unpack2(acc[i][3]);
            int c0 = cg * 8;
            float4 ya = make_float4(
                fmaxf(p0.x * s1[c0]     + t1[c0],     0.f),
                fmaxf(p0.y * s1[c0 + 1] + t1[c0 + 1], 0.f),
                fmaxf(p1.x * s1[c0 + 2] + t1[c0 + 2], 0.f),
                fmaxf(p1.y * s1[c0 + 3] + t1[c0 + 3], 0.f));
            float4 yb = make_float4(
                fmaxf(p2.x * s1[c0 + 4] + t1[c0 + 4], 0.f),
                fmaxf(p2.y * s1[c0 + 5] + t1[c0 + 5], 0.f),
                fmaxf(p3.x * s1[c0 + 6] + t1[c0 + 6], 0.f),
                fmaxf(p3.y * s1[c0 + 7] + t1[c0 + 7], 0.f));
            float* pp = g_pool + b * HD + c0;
            red_add_f4(pp, ya);
            red_add_f4(pp + 4, yb);
        }
    }
}

// ---------------------------------------------------------------------------
// K8: per graph: xt = relu(topo@Wt+bt); out = [pool, xt] @ Wc + bc
// Also: cleanup for next replay (zero deg/state and pool-after-read).
// ---------------------------------------------------------------------------
__global__ void final_kernel(const float* __restrict__ topo,
                             const float* __restrict__ Wt, const float* __restrict__ bt,
                             const float* __restrict__ Wc, const float* __restrict__ bc,
                             float* __restrict__ out, int B, int C, int N) {
    int b = blockIdx.x;
    int t = threadIdx.x;   // 64
    __shared__ float comb[128];

    float acc = bt[t];
    #pragma unroll
    for (int k = 0; k < 64; k++)
        acc += topo[b * 64 + k] * Wt[k * 64 + t];
    comb[64 + t] = fmaxf(acc, 0.f);
    comb[t] = g_pool[b * HD + t];
    __syncthreads();

    if (t < C) {
        float o = bc[t];
        #pragma unroll
        for (int k = 0; k < 128; k++)
            o += comb[k] * Wc[k * C + t];
        out[b * C + t] = o;
    }

    // cleanup for next replay
    g_pool[b * HD + t] = 0.f;                 // read above (pre-sync), safe
    int gidx = b * 64 + t;
    for (int i = gidx; i < N; i += B * 64) g_deg[i] = 0;
    if (gidx < 128) g_state[gidx] = 0ull;
}

// ---------------------------------------------------------------------------
extern "C" void kernel_launch(void* const* d_in, const int* in_sizes, int n_in,
                              void* d_out, int out_size) {
    const float* x     = (const float*)d_in[0];
    const int*   ei    = (const int*)  d_in[1];
    const int*   batch = (const int*)  d_in[2];
    const float* topo  = (const float*)d_in[3];
    const float* W1a = (const float*)d_in[4];
    const float* b1a = (const float*)d_in[5];
    const float* g1  = (const float*)d_in[6];
    const float* be1 = (const float*)d_in[7];
    const float* m1  = (const float*)d_in[8];
    const float* v1  = (const float*)d_in[9];
    const float* W1b = (const float*)d_in[10];
    const float* b1b = (const float*)d_in[11];
    const float* W2  = (const float*)d_in[12];
    const float* b2  = (const float*)d_in[13];
    const float* g2  = (const float*)d_in[14];
    const float* be2 = (const float*)d_in[15];
    const float* m2  = (const float*)d_in[16];
    const float* v2  = (const float*)d_in[17];
    const float* Wt  = (const float*)d_in[18];
    const float* bt  = (const float*)d_in[19];
    const float* Wc  = (const float*)d_in[20];
    const float* bc  = (const float*)d_in[21];
    float* out = (float*)d_out;

    int N = in_sizes[0] / HD;        // nodes
    int E = in_sizes[1] / 2;         // edges
    int B = in_sizes[3] / HD;        // graphs
    int C = out_size / B;            // classes

    static const int MLP1_SMEM = (2 * 64 * WSTRIDE + 128 * 65 + 128) * (int)sizeof(float);
    static const int MLP2_SMEM = (64 * WSTRIDE + 128 * 65 + 128) * (int)sizeof(float);
    cudaFuncSetAttribute(mlp1_kernel, cudaFuncAttributeMaxDynamicSharedMemorySize, MLP1_SMEM);
    cudaFuncSetAttribute(mlp2_kernel, cudaFuncAttributeMaxDynamicSharedMemorySize, MLP2_SMEM);

    int nv4 = (E >> 2);
    hist_kernel<<<(nv4 + 255) / 256, 256>>>(ei, E);

    int nb = (N + 1023) / 1024;
    scan_kernel<<<nb, 1024>>>(N);

    permute_kernel<<<(nv4 + 255) / 256, 256>>>(ei, E);

    int aBlocks = (N * 32 + 255) / 256;
    int mBlocks = (N + 127) / 128;

    agg_kernel<<<aBlocks, 256>>>(x, 0, N);   // x -> g_agg
    mlp1_kernel<<<mBlocks, 128, MLP1_SMEM>>>(W1a, b1a, g1, be1, m1, v1, W1b, b1b, N);
    agg_kernel<<<aBlocks, 256>>>(x, 1, N);   // g_h -> g_agg
    mlp2_kernel<<<mBlocks, 128, MLP2_SMEM>>>(W2, b2, g2, be2, m2, v2, batch, N);

    final_kernel<<<B, 64>>>(topo, Wt, bt, Wc, bc, out, B, C, N);
}